// round 13
// baseline (speedup 1.0000x reference)
#include <cuda_runtime.h>
#include <cstdint>

// Problem constants
// B=32, L=512, E=H=512, G=4H=2048, N=2 layers, V=32000
#define NB 32
#define NL 512
#define NH 512
#define NG 2048
#define NLAYERS 2

// Scratch (static device globals -- allocation-free)
__device__ float g_xg[(size_t)NL * NB * NG];   // (L*B, 4H) layer-0 gate preacts (input part + bias)
__device__ float g_h0[4 * NH * NB];            // 4-slot ring, h layer0, [slot][j][b]
__device__ float g_h1[4 * NH * NB];            // 4-slot ring, h layer1, [slot][j][b]
__device__ int   g_bar;                        // global barrier counter

// ---------------------------------------------------------------------------
// Packed f32x2 helpers (fma.rn.f32x2 -- 2 fp32 MACs per instruction)
// ---------------------------------------------------------------------------
__device__ __forceinline__ unsigned long long ffma2(unsigned long long a,
                                                    unsigned long long b,
                                                    unsigned long long c) {
    unsigned long long d;
    asm("fma.rn.f32x2 %0, %1, %2, %3;" : "=l"(d) : "l"(a), "l"(b), "l"(c));
    return d;
}
__device__ __forceinline__ unsigned long long addf2(unsigned long long a,
                                                    unsigned long long b) {
    unsigned long long d;
    asm("add.rn.f32x2 %0, %1, %2;" : "=l"(d) : "l"(a), "l"(b));
    return d;
}
__device__ __forceinline__ unsigned long long pack2(float x) {
    unsigned long long d;
    asm("mov.b64 %0, {%1, %1};" : "=l"(d) : "f"(x));
    return d;
}
__device__ __forceinline__ float2 unpack2(unsigned long long u) {
    float2 f;
    asm("mov.b64 {%0, %1}, %2;" : "=f"(f.x), "=f"(f.y) : "l"(u));
    return f;
}

__device__ __forceinline__ float sigm_f(float x) {
    return 1.f / (1.f + __expf(-x));
}
// tanh via exp, precise division; clamp avoids inf/inf NaN. err ~1e-6 rel.
__device__ __forceinline__ float tanh_f(float x) {
    float xx = fminf(fmaxf(x, -15.f), 15.f);
    float e = __expf(2.f * xx);
    return (e - 1.f) / (e + 1.f);
}

// ---------------------------------------------------------------------------
// init: zero h rings + barrier counter
// ---------------------------------------------------------------------------
__global__ void init_kernel() {
    int i = blockIdx.x * blockDim.x + threadIdx.x;
    int stride = gridDim.x * blockDim.x;
    for (int j = i; j < 4 * NH * NB; j += stride) { g_h0[j] = 0.f; g_h1[j] = 0.f; }
    if (i == 0) g_bar = 0;
}

// ---------------------------------------------------------------------------
// xg GEMM (layer 0 only): xg[m][n] = emb[tokens] @ Wih0^T + (bih0+bhh0)
// 128x128x8 tile, 256 threads, 8x8 microtile, FFMA2 inner product.
// ---------------------------------------------------------------------------
__global__ __launch_bounds__(256) void xg_gemm(
    const float* __restrict__ emb,
    const int*   __restrict__ tokens,
    const float* __restrict__ W,        // (2048, 512) row-major
    const float* __restrict__ bih_l,
    const float* __restrict__ bhh_l)
{
    __shared__ float As[8][128];
    __shared__ float Bs[8][128];
    __shared__ float bias_s[128];

    const int tid = threadIdx.x;
    const int n0 = blockIdx.x * 128;
    const int m0 = blockIdx.y * 128;

    if (tid < 128) bias_s[tid] = bih_l[n0 + tid] + bhh_l[n0 + tid];

    const int lr = tid >> 1;          // 0..127 tile row for loading
    const int kq = (tid & 1) * 4;     // 0 or 4

    const float* arow;
    {
        int m = m0 + lr;
        int t = m >> 5, b = m & 31;
        int tok = tokens[b * NL + t];
        arow = emb + (size_t)tok * 512;
    }
    const float* brow = W + (size_t)(n0 + lr) * 512;

    const int tm = (tid >> 4) * 8;
    const int tn = (tid & 15) * 8;

    unsigned long long acc2[8][4];    // 8 rows x 4 f32x2 pairs (8 cols)
#pragma unroll
    for (int i = 0; i < 8; i++)
#pragma unroll
        for (int p = 0; p < 4; p++) acc2[i][p] = 0ull;

    for (int k0 = 0; k0 < 512; k0 += 8) {
        float4 av = *(const float4*)(arow + k0 + kq);
        float4 bv = *(const float4*)(brow + k0 + kq);
        __syncthreads();
        As[kq + 0][lr] = av.x; As[kq + 1][lr] = av.y;
        As[kq + 2][lr] = av.z; As[kq + 3][lr] = av.w;
        Bs[kq + 0][lr] = bv.x; Bs[kq + 1][lr] = bv.y;
        Bs[kq + 2][lr] = bv.z; Bs[kq + 3][lr] = bv.w;
        __syncthreads();
#pragma unroll
        for (int kk = 0; kk < 8; kk++) {
            float a[8];
            *(float4*)(a)     = *(const float4*)(&As[kk][tm]);
            *(float4*)(a + 4) = *(const float4*)(&As[kk][tm + 4]);
            ulonglong2 b01 = *(const ulonglong2*)(&Bs[kk][tn]);
            ulonglong2 b23 = *(const ulonglong2*)(&Bs[kk][tn + 4]);
#pragma unroll
            for (int i = 0; i < 8; i++) {
                unsigned long long ad = pack2(a[i]);
                acc2[i][0] = ffma2(ad, b01.x, acc2[i][0]);
                acc2[i][1] = ffma2(ad, b01.y, acc2[i][1]);
                acc2[i][2] = ffma2(ad, b23.x, acc2[i][2]);
                acc2[i][3] = ffma2(ad, b23.y, acc2[i][3]);
            }
        }
    }

    ulonglong2 bi01 = *(const ulonglong2*)(&bias_s[tn]);
    ulonglong2 bi23 = *(const ulonglong2*)(&bias_s[tn + 4]);
#pragma unroll
    for (int i = 0; i < 8; i++) {
        float* orow = g_xg + (size_t)(m0 + tm + i) * NG + n0 + tn;
        ulonglong2 o0, o1;
        o0.x = addf2(acc2[i][0], bi01.x);
        o0.y = addf2(acc2[i][1], bi01.y);
        o1.x = addf2(acc2[i][2], bi23.x);
        o1.y = addf2(acc2[i][3], bi23.y);
        *(ulonglong2*)(orow)     = o0;
        *(ulonglong2*)(orow + 4) = o1;
    }
}

// ---------------------------------------------------------------------------
// Fused 2-layer pipelined LSTM recurrence, barrier-hiding schedule.
// 128 CTAs x 512 threads (16 warps). Step s (s = 0 .. NL+1):
//   B1 (pre-barrier): Wih1 @ h0[s-2]   (stale operand, hides barrier wait)
//   wait count >= 128*s  (publishes h0[s-1], h1[s-3])
//   A : Whh0 @ h0[s-1]                 (layer0 t=s,   active s<NL)
//   B2: Whh1 @ h1[s-3] (+= into B1)    (layer1 t=s-2, active s>=2)
//   reduce + gates + store h0[s], h1[s-2]; release-arrive.
// K split 16 ways (32 k per warp); weights non-duplicated in smem, FFMA2
// row-paired; h via plain LDG (L2) -- acquire/release barrier keeps coherence.
// ---------------------------------------------------------------------------
#define REDSZ (16 * 16 * 33)   // [warp 0..15][row 0..15] stride-33 padded

__global__ __launch_bounds__(512, 1) void lstm_fused(
    const float* __restrict__ Whh,     // (2, 2048, 512)
    const float* __restrict__ Wih,     // (2, 2048, 512)
    const float* __restrict__ bih,     // (2, 2048)
    const float* __restrict__ bhh,     // (2, 2048)
    float* __restrict__ d_out)
{
    extern __shared__ float sm[];
    float* w0   = sm;                    // 512*16 floats (Whh0 slice, [k][row])
    float* w1i  = w0  + 512 * 16;        // 512*16       (Wih1 slice)
    float* w1h  = w1i + 512 * 16;        // 512*16       (Whh1 slice)
    float* redA = w1h + 512 * 16;        // REDSZ
    float* redB = redA + REDSZ;          // REDSZ
    float* c0_s = redB + REDSZ;          // 128
    float* c1_s = c0_s + 128;            // 128

    const int tid = threadIdx.x;
    const int cta = blockIdx.x;          // 0..127 -> units [cta*4, cta*4+4)

    // One-time: load 3 weight slices (16 gate rows each), [k][row] layout
    for (int idx = tid; idx < 3 * 16 * 512; idx += 512) {
        int slice = idx >> 13;           // 0..2
        int rem   = idx & 8191;
        int lrw   = rem >> 9;            // 0..15 (q*4+u)
        int k     = rem & 511;
        int row   = (lrw >> 2) * 512 + cta * 4 + (lrw & 3);
        const float* src = (slice == 0) ? Whh
                         : (slice == 1) ? (Wih + (size_t)NG * NH)
                                        : (Whh + (size_t)NG * NH);
        float v = src[(size_t)row * 512 + k];
        float* dst = (slice == 0) ? w0 : (slice == 1) ? w1i : w1h;
        dst[k * 16 + lrw] = v;
    }
    if (tid < 128) { c0_s[tid] = 0.f; c1_s[tid] = 0.f; }
    __syncthreads();

    const int lane = tid & 31, warp = tid >> 5;   // warp 0..15
    const int rg = lane >> 3, bg = lane & 7;      // rg: 4 rows, bg: 4 batch
    const int k0 = warp * 32;                     // 32-k slice per warp

    // Gate-thread constants (tid < 256): set = tid>>7, u = (tid>>5)&3, b = tid&31
    const int gset = tid >> 7, uu = (tid >> 5) & 3, bb = tid & 31;
    int   rowq[4];
    float b1[4];
    if (tid < 256) {
#pragma unroll
        for (int q = 0; q < 4; q++) {
            rowq[q] = q * 512 + cta * 4 + uu;
            b1[q] = bih[NG + rowq[q]] + bhh[NG + rowq[q]];
        }
    }

    const float* w0b  = w0  + rg * 4;
    const float* w1ib = w1i + rg * 4;
    const float* w1hb = w1h + rg * 4;

    for (int s = 0; s <= NL + 1; s++) {
        const bool l0_act = (s < NL);
        const bool l1_act = (s >= 2);

        // Prefetch layer-0 xg for this step (set-A gate threads)
        float xg0[4];
        if (tid < 128 && l0_act) {
            const float* xp = g_xg + (size_t)(s * 32 + bb) * NG;
#pragma unroll
            for (int q = 0; q < 4; q++) xg0[q] = __ldg(xp + rowq[q]);
        }

        // ---- B1 (pre-barrier): Wih1 @ h0[(s-2)&3] -- stale, no wait needed
        unsigned long long Bv[8];
#pragma unroll
        for (int i = 0; i < 8; i++) Bv[i] = 0ull;
        if (l1_act) {
            const float* hp = g_h0 + ((s - 2) & 3) * (NH * NB) + bg * 4;
#pragma unroll 8
            for (int k = k0; k < k0 + 32; k++) {
                float4 hv = *(const float4*)(hp + k * 32);
                unsigned long long d0 = pack2(hv.x), d1 = pack2(hv.y);
                unsigned long long d2 = pack2(hv.z), d3 = pack2(hv.w);
                ulonglong2 W1 = *(const ulonglong2*)(w1ib + k * 16);
                Bv[0] = ffma2(W1.x, d0, Bv[0]); Bv[1] = ffma2(W1.x, d1, Bv[1]);
                Bv[2] = ffma2(W1.x, d2, Bv[2]); Bv[3] = ffma2(W1.x, d3, Bv[3]);
                Bv[4] = ffma2(W1.y, d0, Bv[4]); Bv[5] = ffma2(W1.y, d1, Bv[5]);
                Bv[6] = ffma2(W1.y, d2, Bv[6]); Bv[7] = ffma2(W1.y, d3, Bv[7]);
            }
        }

        // ---- Grid barrier wait: publishes h0[s-1] and h1[s-3]
        if (s >= 1) {
            if (tid == 0) {
                int target = 128 * s;
                int v;
                do {
                    asm volatile("ld.acquire.gpu.global.s32 %0, [%1];"
                                 : "=r"(v) : "l"(&g_bar) : "memory");
                } while (v < target);
            }
            __syncthreads();
        }

        // ---- A: Whh0 @ h0[(s-1)&3] (fresh)
        unsigned long long A[8];
#pragma unroll
        for (int i = 0; i < 8; i++) A[i] = 0ull;
        if (l0_act) {
            const float* hp = g_h0 + ((s - 1) & 3) * (NH * NB) + bg * 4;
#pragma unroll 8
            for (int k = k0; k < k0 + 32; k++) {
                float4 hv = *(const float4*)(hp + k * 32);
                unsigned long long d0 = pack2(hv.x), d1 = pack2(hv.y);
                unsigned long long d2 = pack2(hv.z), d3 = pack2(hv.w);
                ulonglong2 W0 = *(const ulonglong2*)(w0b + k * 16);
                A[0] = ffma2(W0.x, d0, A[0]); A[1] = ffma2(W0.x, d1, A[1]);
                A[2] = ffma2(W0.x, d2, A[2]); A[3] = ffma2(W0.x, d3, A[3]);
                A[4] = ffma2(W0.y, d0, A[4]); A[5] = ffma2(W0.y, d1, A[5]);
                A[6] = ffma2(W0.y, d2, A[6]); A[7] = ffma2(W0.y, d3, A[7]);
            }
        }

        // ---- B2: Whh1 @ h1[(s-3)&3] (fresh, published last step), += into Bv
        if (l1_act) {
            const float* hp = g_h1 + ((s - 3) & 3) * (NH * NB) + bg * 4;
#pragma unroll 8
            for (int k = k0; k < k0 + 32; k++) {
                float4 hv = *(const float4*)(hp + k * 32);
                unsigned long long d0 = pack2(hv.x), d1 = pack2(hv.y);
                unsigned long long d2 = pack2(hv.z), d3 = pack2(hv.w);
                ulonglong2 W2 = *(const ulonglong2*)(w1hb + k * 16);
                Bv[0] = ffma2(W2.x, d0, Bv[0]); Bv[1] = ffma2(W2.x, d1, Bv[1]);
                Bv[2] = ffma2(W2.x, d2, Bv[2]); Bv[3] = ffma2(W2.x, d3, Bv[3]);
                Bv[4] = ffma2(W2.y, d0, Bv[4]); Bv[5] = ffma2(W2.y, d1, Bv[5]);
                Bv[6] = ffma2(W2.y, d2, Bv[6]); Bv[7] = ffma2(W2.y, d3, Bv[7]);
            }
        }

        // ---- Store partials (pair (x,y) = rows (rg*4+rp*2, +1), batch bg*4+j)
#pragma unroll
        for (int rp = 0; rp < 2; rp++)
#pragma unroll
            for (int j = 0; j < 4; j++) {
                int b = bg * 4 + j;
                int r = rg * 4 + rp * 2;
                if (l0_act) {
                    float2 p = unpack2(A[rp * 4 + j]);
                    redA[(warp * 16 + r + 0) * 33 + b] = p.x;
                    redA[(warp * 16 + r + 1) * 33 + b] = p.y;
                }
                if (l1_act) {
                    float2 p = unpack2(Bv[rp * 4 + j]);
                    redB[(warp * 16 + r + 0) * 33 + b] = p.x;
                    redB[(warp * 16 + r + 1) * 33 + b] = p.y;
                }
            }
        __syncthreads();

        // ---- Fused reduce + gates (tid < 256)
        if (tid < 256) {
            int j = cta * 4 + uu;
            if (gset == 0 && l0_act) {        // layer 0, t = s
                float gq[4];
#pragma unroll
                for (int q = 0; q < 4; q++) {
                    float acc = xg0[q];
                    const float* rp = redA + (q * 4 + uu) * 33 + bb;
#pragma unroll
                    for (int w = 0; w < 16; w++) acc += rp[w * 16 * 33];
                    gq[q] = acc;
                }
                float ig = sigm_f(gq[0]);
                float fg = sigm_f(gq[1]);
                float cg = tanh_f(gq[2]);
                float og = sigm_f(gq[3]);
                int ci = uu * 32 + bb;
                float c = fg * c0_s[ci] + ig * cg;
                c0_s[ci] = c;
                float h = og * tanh_f(c);
                g_h0[(s & 3) * (NH * NB) + j * 32 + bb] = h;
                if (s == NL - 1) {
                    d_out[bb * NH + j] = h;                               // hidden L0
                    d_out[NLAYERS * NB * NH + bb * NH + j] = c;           // cell  L0
                }
            }
            if (gset == 1 && l1_act) {        // layer 1, t = s-2
                float gq[4];
#pragma unroll
                for (int q = 0; q < 4; q++) {
                    float acc = b1[q];
                    const float* rp = redB + (q * 4 + uu) * 33 + bb;
#pragma unroll
                    for (int w = 0; w < 16; w++) acc += rp[w * 16 * 33];
                    gq[q] = acc;
                }
                float ig = sigm_f(gq[0]);
                float fg = sigm_f(gq[1]);
                float cg = tanh_f(gq[2]);
                float og = sigm_f(gq[3]);
                int ci = uu * 32 + bb;
                float c = fg * c1_s[ci] + ig * cg;
                c1_s[ci] = c;
                float h = og * tanh_f(c);
                g_h1[((s - 2) & 3) * (NH * NB) + j * 32 + bb] = h;
                if (s == NL + 1) {
                    d_out[NB * NH + bb * NH + j] = h;                     // hidden L1
                    d_out[NLAYERS * NB * NH + NB * NH + bb * NH + j] = c; // cell  L1
                }
            }
        }
        __syncthreads();

        // ---- Release-arrive (no fence needed: RED carries release semantics,
        //      syncthreads above orders the gate threads' stores before it)
        if (s <= NL) {
            if (tid == 0) {
                asm volatile("red.release.gpu.global.add.s32 [%0], %1;"
                             :: "l"(&g_bar), "r"(1) : "memory");
            }
        }
    }
}

// ---------------------------------------------------------------------------
// Launcher
// ---------------------------------------------------------------------------
extern "C" void kernel_launch(void* const* d_in, const int* in_sizes, int n_in,
                              void* d_out, int out_size) {
    const int*   tokens = (const int*)  d_in[0];
    const float* emb    = (const float*)d_in[1];
    const float* Wih    = (const float*)d_in[2];   // (2, 2048, 512)
    const float* Whh    = (const float*)d_in[3];   // (2, 2048, 512)
    const float* bih    = (const float*)d_in[4];   // (2, 2048)
    const float* bhh    = (const float*)d_in[5];   // (2, 2048)
    float* out = (float*)d_out;

    const int FUSED_SMEM = (3 * 512 * 16 + 2 * REDSZ + 256) * 4;   // 166912 B
    cudaFuncSetAttribute(lstm_fused, cudaFuncAttributeMaxDynamicSharedMemorySize,
                         FUSED_SMEM);

    dim3 ggrid(NG / 128, (NL * NB) / 128);   // (16, 128)

    // layer-0 input GEMM (embedding gather fused), then fused 2-layer recurrence
    xg_gemm<<<ggrid, 256>>>(emb, tokens, Wih, bih, bhh);
    init_kernel<<<64, 256>>>();
    lstm_fused<<<128, 512, FUSED_SMEM>>>(Whh, Wih, bih, bhh, out);
}

// round 14
// speedup vs baseline: 1.1227x; 1.1227x over previous
#include <cuda_runtime.h>
#include <cstdint>

// Problem constants
// B=32, L=512, E=H=512, G=4H=2048, N=2 layers, V=32000
#define NB 32
#define NL 512
#define NH 512
#define NG 2048
#define NLAYERS 2

// Scratch (static device globals -- allocation-free)
__device__ float g_xg[(size_t)NL * NB * NG];   // (L*B, 4H) layer-0 gate preacts (input part + bias)
__device__ float g_h0[2 * NH * NB];            // double-buffered h layer0, [buf][j][b]
__device__ float g_h1[2 * NH * NB];            // double-buffered h layer1, [buf][j][b]
__device__ int   g_bar;                        // global barrier counter

// ---------------------------------------------------------------------------
// Packed f32x2 helpers (fma.rn.f32x2 -- 2 fp32 MACs per instruction)
// ---------------------------------------------------------------------------
__device__ __forceinline__ unsigned long long ffma2(unsigned long long a,
                                                    unsigned long long b,
                                                    unsigned long long c) {
    unsigned long long d;
    asm("fma.rn.f32x2 %0, %1, %2, %3;" : "=l"(d) : "l"(a), "l"(b), "l"(c));
    return d;
}
__device__ __forceinline__ unsigned long long addf2(unsigned long long a,
                                                    unsigned long long b) {
    unsigned long long d;
    asm("add.rn.f32x2 %0, %1, %2;" : "=l"(d) : "l"(a), "l"(b));
    return d;
}
__device__ __forceinline__ unsigned long long pack2(float x) {
    unsigned long long d;
    asm("mov.b64 %0, {%1, %1};" : "=l"(d) : "f"(x));
    return d;
}
__device__ __forceinline__ float2 unpack2(unsigned long long u) {
    float2 f;
    asm("mov.b64 {%0, %1}, %2;" : "=f"(f.x), "=f"(f.y) : "l"(u));
    return f;
}

__device__ __forceinline__ float rcp_fast(float x) {
    float r;
    asm("rcp.approx.f32 %0, %1;" : "=f"(r) : "f"(x));
    return r;
}
__device__ __forceinline__ float sigm_f(float x) {
    return rcp_fast(1.f + __expf(-x));
}
// tanh via exp + approx reciprocal; clamp avoids inf/inf. err ~1e-6 rel.
__device__ __forceinline__ float tanh_f(float x) {
    float xx = fminf(fmaxf(x, -15.f), 15.f);
    float e = __expf(2.f * xx);
    return (e - 1.f) * rcp_fast(e + 1.f);
}

// ---------------------------------------------------------------------------
// init: zero h states + barrier counter
// ---------------------------------------------------------------------------
__global__ void init_kernel() {
    int i = blockIdx.x * blockDim.x + threadIdx.x;
    int stride = gridDim.x * blockDim.x;
    for (int j = i; j < 2 * NH * NB; j += stride) { g_h0[j] = 0.f; g_h1[j] = 0.f; }
    if (i == 0) g_bar = 0;
}

// ---------------------------------------------------------------------------
// xg GEMM (layer 0 only): xg[m][n] = emb[tokens] @ Wih0^T + (bih0+bhh0)
// 128x128x8 tile, 256 threads, 8x8 microtile with SPLIT-COLUMN ownership
// (cols tn4..tn4+3 and tn4+64..tn4+67, tn4=(tid&15)*4) -- 8 lanes of each
// LDS.128 phase cover all 32 banks: conflict-free B reads. Smem rows padded
// to 132 floats: conflict-free tile stores.
// ---------------------------------------------------------------------------
#define XROW 132

__global__ __launch_bounds__(256) void xg_gemm(
    const float* __restrict__ emb,
    const int*   __restrict__ tokens,
    const float* __restrict__ W,        // (2048, 512) row-major
    const float* __restrict__ bih_l,
    const float* __restrict__ bhh_l)
{
    __shared__ float As[8 * XROW];
    __shared__ float Bs[8 * XROW];
    __shared__ float bias_s[128];

    const int tid = threadIdx.x;
    const int n0 = blockIdx.x * 128;
    const int m0 = blockIdx.y * 128;

    if (tid < 128) bias_s[tid] = bih_l[n0 + tid] + bhh_l[n0 + tid];

    const int lr = tid >> 1;          // 0..127 tile row for loading
    const int kq = (tid & 1) * 4;     // 0 or 4

    const float* arow;
    {
        int m = m0 + lr;
        int t = m >> 5, b = m & 31;
        int tok = tokens[b * NL + t];
        arow = emb + (size_t)tok * 512;
    }
    const float* brow = W + (size_t)(n0 + lr) * 512;

    const int tm  = (tid >> 4) * 8;   // 8 rows
    const int tn4 = (tid & 15) * 4;   // cols tn4..tn4+3 and tn4+64..tn4+67

    unsigned long long acc2[8][4];    // [row][pair]: pairs 0-1 -> tn4+{0,2}, 2-3 -> tn4+64+{0,2}
#pragma unroll
    for (int i = 0; i < 8; i++)
#pragma unroll
        for (int p = 0; p < 4; p++) acc2[i][p] = 0ull;

    for (int k0 = 0; k0 < 512; k0 += 8) {
        float4 av = *(const float4*)(arow + k0 + kq);
        float4 bv = *(const float4*)(brow + k0 + kq);
        __syncthreads();
        As[(kq + 0) * XROW + lr] = av.x; As[(kq + 1) * XROW + lr] = av.y;
        As[(kq + 2) * XROW + lr] = av.z; As[(kq + 3) * XROW + lr] = av.w;
        Bs[(kq + 0) * XROW + lr] = bv.x; Bs[(kq + 1) * XROW + lr] = bv.y;
        Bs[(kq + 2) * XROW + lr] = bv.z; Bs[(kq + 3) * XROW + lr] = bv.w;
        __syncthreads();
#pragma unroll
        for (int kk = 0; kk < 8; kk++) {
            float a[8];
            *(float4*)(a)     = *(const float4*)(&As[kk * XROW + tm]);
            *(float4*)(a + 4) = *(const float4*)(&As[kk * XROW + tm + 4]);
            ulonglong2 b01 = *(const ulonglong2*)(&Bs[kk * XROW + tn4]);
            ulonglong2 b23 = *(const ulonglong2*)(&Bs[kk * XROW + tn4 + 64]);
#pragma unroll
            for (int i = 0; i < 8; i++) {
                unsigned long long ad = pack2(a[i]);
                acc2[i][0] = ffma2(ad, b01.x, acc2[i][0]);
                acc2[i][1] = ffma2(ad, b01.y, acc2[i][1]);
                acc2[i][2] = ffma2(ad, b23.x, acc2[i][2]);
                acc2[i][3] = ffma2(ad, b23.y, acc2[i][3]);
            }
        }
    }

    ulonglong2 bi01 = *(const ulonglong2*)(&bias_s[tn4]);
    ulonglong2 bi23 = *(const ulonglong2*)(&bias_s[tn4 + 64]);
#pragma unroll
    for (int i = 0; i < 8; i++) {
        float* orow = g_xg + (size_t)(m0 + tm + i) * NG + n0;
        ulonglong2 o0, o1;
        o0.x = addf2(acc2[i][0], bi01.x);
        o0.y = addf2(acc2[i][1], bi01.y);
        o1.x = addf2(acc2[i][2], bi23.x);
        o1.y = addf2(acc2[i][3], bi23.y);
        *(ulonglong2*)(orow + tn4)      = o0;
        *(ulonglong2*)(orow + tn4 + 64) = o1;
    }
}

// ---------------------------------------------------------------------------
// Fused 2-layer pipelined LSTM recurrence (R12 merged-loop schedule).
// 128 CTAs x 512 threads (16 warps). Fused step s (s = 0..512):
//   layer0 computes t=s      (active s<512): gA = Whh0 @ h0[s-1]
//   layer1 computes t=s-1    (active s>=1) : gB = Wih1 @ h0[s-1] + Whh1 @ h1[s-2]
// K split 16 ways (32 k per warp). Weights NON-duplicated in smem; FFMA2 pairs
// over adjacent gate rows, h scalars dup'd via pack2 (ALU pipe, hidden under
// fma). h via plain LDG (L2); release-RED / acquire-load keep coherence.
// ---------------------------------------------------------------------------
#define REDSZ (16 * 16 * 33)   // [warp 0..15][row 0..15] stride-33 padded

__global__ __launch_bounds__(512, 1) void lstm_fused(
    const float* __restrict__ Whh,     // (2, 2048, 512)
    const float* __restrict__ Wih,     // (2, 2048, 512)
    const float* __restrict__ bih,     // (2, 2048)
    const float* __restrict__ bhh,     // (2, 2048)
    float* __restrict__ d_out)
{
    extern __shared__ float sm[];
    float* w0   = sm;                    // 512*16 floats (Whh0 slice, [k][row])
    float* w1i  = w0  + 512 * 16;        // 512*16       (Wih1 slice)
    float* w1h  = w1i + 512 * 16;        // 512*16       (Whh1 slice)
    float* redA = w1h + 512 * 16;        // REDSZ
    float* redB = redA + REDSZ;          // REDSZ
    float* c0_s = redB + REDSZ;          // 128
    float* c1_s = c0_s + 128;            // 128

    const int tid = threadIdx.x;
    const int cta = blockIdx.x;          // 0..127 -> units [cta*4, cta*4+4)

    // One-time: load 3 weight slices (16 gate rows each), [k][row] layout
    for (int idx = tid; idx < 3 * 16 * 512; idx += 512) {
        int slice = idx >> 13;           // 0..2
        int rem   = idx & 8191;
        int lrw   = rem >> 9;            // 0..15 (q*4+u)
        int k     = rem & 511;
        int row   = (lrw >> 2) * 512 + cta * 4 + (lrw & 3);
        const float* src = (slice == 0) ? Whh
                         : (slice == 1) ? (Wih + (size_t)NG * NH)
                                        : (Whh + (size_t)NG * NH);
        float v = src[(size_t)row * 512 + k];
        float* dst = (slice == 0) ? w0 : (slice == 1) ? w1i : w1h;
        dst[k * 16 + lrw] = v;
    }
    if (tid < 128) { c0_s[tid] = 0.f; c1_s[tid] = 0.f; }
    __syncthreads();

    const int lane = tid & 31, warp = tid >> 5;   // warp 0..15
    const int rg = lane >> 3, bg = lane & 7;      // rg: 4 rows, bg: 4 batch
    const int k0 = warp * 32;                     // 32-k slice per warp

    // Gate-thread constants (tid < 256): set = tid>>7, u = (tid>>5)&3, b = tid&31
    const int gset = tid >> 7, uu = (tid >> 5) & 3, bb = tid & 31;
    int   rowq[4];
    float b1[4];
    if (tid < 256) {
#pragma unroll
        for (int q = 0; q < 4; q++) {
            rowq[q] = q * 512 + cta * 4 + uu;
            b1[q] = bih[NG + rowq[q]] + bhh[NG + rowq[q]];
        }
    }

    const float* w0b  = w0  + rg * 4;
    const float* w1ib = w1i + rg * 4;
    const float* w1hb = w1h + rg * 4;

    for (int s = 0; s <= NL; s++) {
        // Prefetch layer-0 xg for this step (set-A gate threads)
        float xg0[4];
        if (tid < 128) {
            int t0 = (s < NL) ? s : (NL - 1);
            const float* xp = g_xg + (size_t)(t0 * 32 + bb) * NG;
#pragma unroll
            for (int q = 0; q < 4; q++) xg0[q] = __ldg(xp + rowq[q]);
        }

        // h pointers (previous-step state; buffers alternate)
        const float* h0p = g_h0 + (s & 1) * (NH * NB) + bg * 4;
        const float* h1p = g_h1 + ((s & 1) ^ 1) * (NH * NB) + bg * 4;

        // Merged GEMM: A = Whh0@h0, B = Wih1@h0 + Whh1@h1.
        // Row-paired f32x2: accumulator X[rp*4+j] holds rows
        // (rg*4+rp*2, rg*4+rp*2+1) for batch bg*4+j.
        unsigned long long A[8], Bv[8];
#pragma unroll
        for (int i = 0; i < 8; i++) { A[i] = 0ull; Bv[i] = 0ull; }

#pragma unroll 8
        for (int k = k0; k < k0 + 32; k++) {
            float4 h0v = *(const float4*)(h0p + k * 32);   // LDG (L2)
            float4 h1v = *(const float4*)(h1p + k * 32);   // LDG (L2)
            unsigned long long d00 = pack2(h0v.x), d01 = pack2(h0v.y);
            unsigned long long d02 = pack2(h0v.z), d03 = pack2(h0v.w);
            unsigned long long d10 = pack2(h1v.x), d11 = pack2(h1v.y);
            unsigned long long d12 = pack2(h1v.z), d13 = pack2(h1v.w);

            ulonglong2 W0 = *(const ulonglong2*)(w0b + k * 16);
            A[0] = ffma2(W0.x, d00, A[0]); A[1] = ffma2(W0.x, d01, A[1]);
            A[2] = ffma2(W0.x, d02, A[2]); A[3] = ffma2(W0.x, d03, A[3]);
            A[4] = ffma2(W0.y, d00, A[4]); A[5] = ffma2(W0.y, d01, A[5]);
            A[6] = ffma2(W0.y, d02, A[6]); A[7] = ffma2(W0.y, d03, A[7]);

            ulonglong2 W1 = *(const ulonglong2*)(w1ib + k * 16);
            Bv[0] = ffma2(W1.x, d00, Bv[0]); Bv[1] = ffma2(W1.x, d01, Bv[1]);
            Bv[2] = ffma2(W1.x, d02, Bv[2]); Bv[3] = ffma2(W1.x, d03, Bv[3]);
            Bv[4] = ffma2(W1.y, d00, Bv[4]); Bv[5] = ffma2(W1.y, d01, Bv[5]);
            Bv[6] = ffma2(W1.y, d02, Bv[6]); Bv[7] = ffma2(W1.y, d03, Bv[7]);

            ulonglong2 W2 = *(const ulonglong2*)(w1hb + k * 16);
            Bv[0] = ffma2(W2.x, d10, Bv[0]); Bv[1] = ffma2(W2.x, d11, Bv[1]);
            Bv[2] = ffma2(W2.x, d12, Bv[2]); Bv[3] = ffma2(W2.x, d13, Bv[3]);
            Bv[4] = ffma2(W2.y, d10, Bv[4]); Bv[5] = ffma2(W2.y, d11, Bv[5]);
            Bv[6] = ffma2(W2.y, d12, Bv[6]); Bv[7] = ffma2(W2.y, d13, Bv[7]);
        }

        // Store partials: pair (p.x, p.y) = rows (rg*4+rp*2, +1), batch bg*4+j
#pragma unroll
        for (int rp = 0; rp < 2; rp++)
#pragma unroll
            for (int j = 0; j < 4; j++) {
                int b = bg * 4 + j;
                int r = rg * 4 + rp * 2;
                float2 p = unpack2(A[rp * 4 + j]);
                redA[(warp * 16 + r + 0) * 33 + b] = p.x;
                redA[(warp * 16 + r + 1) * 33 + b] = p.y;
                p = unpack2(Bv[rp * 4 + j]);
                redB[(warp * 16 + r + 0) * 33 + b] = p.x;
                redB[(warp * 16 + r + 1) * 33 + b] = p.y;
            }
        __syncthreads();

        // Fused reduce + gates (tid < 256: set A: tid<128 layer0, set B: layer1)
        if (tid < 256) {
            int j = cta * 4 + uu;
            if (gset == 0 && s < NL) {        // layer 0, t = s
                float gq[4];
#pragma unroll
                for (int q = 0; q < 4; q++) {
                    float acc = xg0[q];
                    const float* rp = redA + (q * 4 + uu) * 33 + bb;
#pragma unroll
                    for (int w = 0; w < 16; w++) acc += rp[w * 16 * 33];
                    gq[q] = acc;
                }
                float ig = sigm_f(gq[0]);
                float fg = sigm_f(gq[1]);
                float cg = tanh_f(gq[2]);
                float og = sigm_f(gq[3]);
                int ci = uu * 32 + bb;
                float c = fg * c0_s[ci] + ig * cg;
                c0_s[ci] = c;
                float h = og * tanh_f(c);
                g_h0[((s + 1) & 1) * (NH * NB) + j * 32 + bb] = h;
                if (s == NL - 1) {
                    d_out[bb * NH + j] = h;                               // hidden L0
                    d_out[NLAYERS * NB * NH + bb * NH + j] = c;           // cell  L0
                }
            }
            if (gset == 1 && s >= 1) {        // layer 1, t = s-1
                float gq[4];
#pragma unroll
                for (int q = 0; q < 4; q++) {
                    float acc = b1[q];
                    const float* rp = redB + (q * 4 + uu) * 33 + bb;
#pragma unroll
                    for (int w = 0; w < 16; w++) acc += rp[w * 16 * 33];
                    gq[q] = acc;
                }
                float ig = sigm_f(gq[0]);
                float fg = sigm_f(gq[1]);
                float cg = tanh_f(gq[2]);
                float og = sigm_f(gq[3]);
                int ci = uu * 32 + bb;
                float c = fg * c1_s[ci] + ig * cg;
                c1_s[ci] = c;
                float h = og * tanh_f(c);
                g_h1[(s & 1) * (NH * NB) + j * 32 + bb] = h;
                if (s == NL) {
                    d_out[NB * NH + bb * NH + j] = h;                     // hidden L1
                    d_out[NLAYERS * NB * NH + NB * NH + bb * NH + j] = c; // cell  L1
                }
            }
        }
        __syncthreads();

        // Grid-wide barrier: release-RED arrive (syncthreads above ordered the
        // gate threads' h stores), then acquire-poll. No MEMBAR needed.
        if (s < NL) {
            if (tid == 0) {
                asm volatile("red.release.gpu.global.add.s32 [%0], %1;"
                             :: "l"(&g_bar), "r"(1) : "memory");
                int target = 128 * (s + 1);
                int v;
                do {
                    asm volatile("ld.acquire.gpu.global.s32 %0, [%1];"
                                 : "=r"(v) : "l"(&g_bar) : "memory");
                } while (v < target);
            }
            __syncthreads();
        }
    }
}

// ---------------------------------------------------------------------------
// Launcher
// ---------------------------------------------------------------------------
extern "C" void kernel_launch(void* const* d_in, const int* in_sizes, int n_in,
                              void* d_out, int out_size) {
    const int*   tokens = (const int*)  d_in[0];
    const float* emb    = (const float*)d_in[1];
    const float* Wih    = (const float*)d_in[2];   // (2, 2048, 512)
    const float* Whh    = (const float*)d_in[3];   // (2, 2048, 512)
    const float* bih    = (const float*)d_in[4];   // (2, 2048)
    const float* bhh    = (const float*)d_in[5];   // (2, 2048)
    float* out = (float*)d_out;

    const int FUSED_SMEM = (3 * 512 * 16 + 2 * REDSZ + 256) * 4;   // 166912 B
    cudaFuncSetAttribute(lstm_fused, cudaFuncAttributeMaxDynamicSharedMemorySize,
                         FUSED_SMEM);

    dim3 ggrid(NG / 128, (NL * NB) / 128);   // (16, 128)

    // layer-0 input GEMM (embedding gather fused), then fused 2-layer recurrence
    xg_gemm<<<ggrid, 256>>>(emb, tokens, Wih, bih, bhh);
    init_kernel<<<64, 256>>>();
    lstm_fused<<<128, 512, FUSED_SMEM>>>(Whh, Wih, bih, bhh, out);
}

// round 15
// speedup vs baseline: 1.1333x; 1.0095x over previous
#include <cuda_runtime.h>
#include <cstdint>

// Problem constants
// B=32, L=512, E=H=512, G=4H=2048, N=2 layers, V=32000
#define NB 32
#define NL 512
#define NH 512
#define NG 2048
#define NLAYERS 2

// Scratch (static device globals -- allocation-free).
// h rings padded +64 floats: the k-loop register pipeline prefetches one
// iteration past the slice end (value unused, must not fault).
__device__ float g_xg[(size_t)NL * NB * NG];   // (L*B, 4H) layer-0 gate preacts (input part + bias)
__device__ float g_h0[2 * NH * NB + 64];       // double-buffered h layer0, [buf][j][b]
__device__ float g_h1[2 * NH * NB + 64];       // double-buffered h layer1, [buf][j][b]
__device__ int   g_bar;                        // global barrier counter

// ---------------------------------------------------------------------------
// Packed f32x2 helpers (fma.rn.f32x2 -- 2 fp32 MACs per instruction)
// ---------------------------------------------------------------------------
__device__ __forceinline__ unsigned long long ffma2(unsigned long long a,
                                                    unsigned long long b,
                                                    unsigned long long c) {
    unsigned long long d;
    asm("fma.rn.f32x2 %0, %1, %2, %3;" : "=l"(d) : "l"(a), "l"(b), "l"(c));
    return d;
}
__device__ __forceinline__ unsigned long long addf2(unsigned long long a,
                                                    unsigned long long b) {
    unsigned long long d;
    asm("add.rn.f32x2 %0, %1, %2;" : "=l"(d) : "l"(a), "l"(b));
    return d;
}
__device__ __forceinline__ unsigned long long pack2(float x) {
    unsigned long long d;
    asm("mov.b64 %0, {%1, %1};" : "=l"(d) : "f"(x));
    return d;
}
__device__ __forceinline__ float2 unpack2(unsigned long long u) {
    float2 f;
    asm("mov.b64 {%0, %1}, %2;" : "=f"(f.x), "=f"(f.y) : "l"(u));
    return f;
}

__device__ __forceinline__ float rcp_fast(float x) {
    float r;
    asm("rcp.approx.f32 %0, %1;" : "=f"(r) : "f"(x));
    return r;
}
__device__ __forceinline__ float sigm_f(float x) {
    return rcp_fast(1.f + __expf(-x));
}
// tanh via exp + approx reciprocal; clamp avoids inf/inf. err ~1e-6 rel.
__device__ __forceinline__ float tanh_f(float x) {
    float xx = fminf(fmaxf(x, -15.f), 15.f);
    float e = __expf(2.f * xx);
    return (e - 1.f) * rcp_fast(e + 1.f);
}

// ---------------------------------------------------------------------------
// init: zero h states + barrier counter
// ---------------------------------------------------------------------------
__global__ void init_kernel() {
    int i = blockIdx.x * blockDim.x + threadIdx.x;
    int stride = gridDim.x * blockDim.x;
    for (int j = i; j < 2 * NH * NB + 64; j += stride) { g_h0[j] = 0.f; g_h1[j] = 0.f; }
    if (i == 0) g_bar = 0;
}

// ---------------------------------------------------------------------------
// xg GEMM (layer 0 only): xg[m][n] = emb[tokens] @ Wih0^T + (bih0+bhh0)
// 128x128x8 tile, 256 threads, 8x8 split-column microtile, 2-STAGE double-
// buffered smem pipeline: next chunk's global loads issued before compute,
// one __syncthreads per chunk.
// ---------------------------------------------------------------------------
#define XROW 132

__global__ __launch_bounds__(256) void xg_gemm(
    const float* __restrict__ emb,
    const int*   __restrict__ tokens,
    const float* __restrict__ W,        // (2048, 512) row-major
    const float* __restrict__ bih_l,
    const float* __restrict__ bhh_l)
{
    __shared__ float As[2][8 * XROW];
    __shared__ float Bs[2][8 * XROW];
    __shared__ float bias_s[128];

    const int tid = threadIdx.x;
    const int n0 = blockIdx.x * 128;
    const int m0 = blockIdx.y * 128;

    if (tid < 128) bias_s[tid] = bih_l[n0 + tid] + bhh_l[n0 + tid];

    const int lr = tid >> 1;          // 0..127 tile row for loading
    const int kq = (tid & 1) * 4;     // 0 or 4

    const float* arow;
    {
        int m = m0 + lr;
        int t = m >> 5, b = m & 31;
        int tok = tokens[b * NL + t];
        arow = emb + (size_t)tok * 512;
    }
    const float* brow = W + (size_t)(n0 + lr) * 512;

    const int tm  = (tid >> 4) * 8;   // 8 rows
    const int tn4 = (tid & 15) * 4;   // cols tn4..tn4+3 and tn4+64..tn4+67

    unsigned long long acc2[8][4];
#pragma unroll
    for (int i = 0; i < 8; i++)
#pragma unroll
        for (int p = 0; p < 4; p++) acc2[i][p] = 0ull;

    // Prologue: chunk 0 into buffer 0
    {
        float4 av = *(const float4*)(arow + kq);
        float4 bv = *(const float4*)(brow + kq);
        As[0][(kq + 0) * XROW + lr] = av.x; As[0][(kq + 1) * XROW + lr] = av.y;
        As[0][(kq + 2) * XROW + lr] = av.z; As[0][(kq + 3) * XROW + lr] = av.w;
        Bs[0][(kq + 0) * XROW + lr] = bv.x; Bs[0][(kq + 1) * XROW + lr] = bv.y;
        Bs[0][(kq + 2) * XROW + lr] = bv.z; Bs[0][(kq + 3) * XROW + lr] = bv.w;
    }
    __syncthreads();

    int buf = 0;
    for (int k0 = 0; k0 < 512; k0 += 8) {
        float4 av, bv;
        const bool more = (k0 + 8) < 512;
        if (more) {                                   // issue next chunk's loads
            av = *(const float4*)(arow + k0 + 8 + kq);
            bv = *(const float4*)(brow + k0 + 8 + kq);
        }
#pragma unroll
        for (int kk = 0; kk < 8; kk++) {
            float a[8];
            *(float4*)(a)     = *(const float4*)(&As[buf][kk * XROW + tm]);
            *(float4*)(a + 4) = *(const float4*)(&As[buf][kk * XROW + tm + 4]);
            ulonglong2 b01 = *(const ulonglong2*)(&Bs[buf][kk * XROW + tn4]);
            ulonglong2 b23 = *(const ulonglong2*)(&Bs[buf][kk * XROW + tn4 + 64]);
#pragma unroll
            for (int i = 0; i < 8; i++) {
                unsigned long long ad = pack2(a[i]);
                acc2[i][0] = ffma2(ad, b01.x, acc2[i][0]);
                acc2[i][1] = ffma2(ad, b01.y, acc2[i][1]);
                acc2[i][2] = ffma2(ad, b23.x, acc2[i][2]);
                acc2[i][3] = ffma2(ad, b23.y, acc2[i][3]);
            }
        }
        if (more) {                                   // fill other buffer, one sync
            int nb = buf ^ 1;
            As[nb][(kq + 0) * XROW + lr] = av.x; As[nb][(kq + 1) * XROW + lr] = av.y;
            As[nb][(kq + 2) * XROW + lr] = av.z; As[nb][(kq + 3) * XROW + lr] = av.w;
            Bs[nb][(kq + 0) * XROW + lr] = bv.x; Bs[nb][(kq + 1) * XROW + lr] = bv.y;
            Bs[nb][(kq + 2) * XROW + lr] = bv.z; Bs[nb][(kq + 3) * XROW + lr] = bv.w;
            __syncthreads();
            buf = nb;
        }
    }

    ulonglong2 bi01 = *(const ulonglong2*)(&bias_s[tn4]);
    ulonglong2 bi23 = *(const ulonglong2*)(&bias_s[tn4 + 64]);
#pragma unroll
    for (int i = 0; i < 8; i++) {
        float* orow = g_xg + (size_t)(m0 + tm + i) * NG + n0;
        ulonglong2 o0, o1;
        o0.x = addf2(acc2[i][0], bi01.x);
        o0.y = addf2(acc2[i][1], bi01.y);
        o1.x = addf2(acc2[i][2], bi23.x);
        o1.y = addf2(acc2[i][3], bi23.y);
        *(ulonglong2*)(orow + tn4)      = o0;
        *(ulonglong2*)(orow + tn4 + 64) = o1;
    }
}

// ---------------------------------------------------------------------------
// Fused 2-layer pipelined LSTM recurrence (validated merged-loop schedule).
// 128 CTAs x 512 threads (16 warps). Fused step s (s = 0..512):
//   layer0 computes t=s      (active s<512): gA = Whh0 @ h0[s-1]
//   layer1 computes t=s-1    (active s>=1) : gB = Wih1 @ h0[s-1] + Whh1 @ h1[s-2]
// K split 16 ways (32 k per warp). Weights non-duplicated in smem, FFMA2
// row-paired. h via plain LDG (L2) with an explicit 1-deep register pipeline:
// iteration k+1's h loads issue before iteration k's FFMA block.
// ---------------------------------------------------------------------------
#define REDSZ (16 * 16 * 33)   // [warp 0..15][row 0..15] stride-33 padded

__global__ __launch_bounds__(512, 1) void lstm_fused(
    const float* __restrict__ Whh,     // (2, 2048, 512)
    const float* __restrict__ Wih,     // (2, 2048, 512)
    const float* __restrict__ bih,     // (2, 2048)
    const float* __restrict__ bhh,     // (2, 2048)
    float* __restrict__ d_out)
{
    extern __shared__ float sm[];
    float* w0   = sm;                    // 512*16 floats (Whh0 slice, [k][row])
    float* w1i  = w0  + 512 * 16;        // 512*16       (Wih1 slice)
    float* w1h  = w1i + 512 * 16;        // 512*16       (Whh1 slice)
    float* redA = w1h + 512 * 16;        // REDSZ
    float* redB = redA + REDSZ;          // REDSZ
    float* c0_s = redB + REDSZ;          // 128
    float* c1_s = c0_s + 128;            // 128

    const int tid = threadIdx.x;
    const int cta = blockIdx.x;          // 0..127 -> units [cta*4, cta*4+4)

    // One-time: load 3 weight slices (16 gate rows each), [k][row] layout
    for (int idx = tid; idx < 3 * 16 * 512; idx += 512) {
        int slice = idx >> 13;           // 0..2
        int rem   = idx & 8191;
        int lrw   = rem >> 9;            // 0..15 (q*4+u)
        int k     = rem & 511;
        int row   = (lrw >> 2) * 512 + cta * 4 + (lrw & 3);
        const float* src = (slice == 0) ? Whh
                         : (slice == 1) ? (Wih + (size_t)NG * NH)
                                        : (Whh + (size_t)NG * NH);
        float v = src[(size_t)row * 512 + k];
        float* dst = (slice == 0) ? w0 : (slice == 1) ? w1i : w1h;
        dst[k * 16 + lrw] = v;
    }
    if (tid < 128) { c0_s[tid] = 0.f; c1_s[tid] = 0.f; }
    __syncthreads();

    const int lane = tid & 31, warp = tid >> 5;   // warp 0..15
    const int rg = lane >> 3, bg = lane & 7;      // rg: 4 rows, bg: 4 batch
    const int k0 = warp * 32;                     // 32-k slice per warp

    // Gate-thread constants (tid < 256): set = tid>>7, u = (tid>>5)&3, b = tid&31
    const int gset = tid >> 7, uu = (tid >> 5) & 3, bb = tid & 31;
    int   rowq[4];
    float b1[4];
    if (tid < 256) {
#pragma unroll
        for (int q = 0; q < 4; q++) {
            rowq[q] = q * 512 + cta * 4 + uu;
            b1[q] = bih[NG + rowq[q]] + bhh[NG + rowq[q]];
        }
    }

    const float* w0b  = w0  + rg * 4;
    const float* w1ib = w1i + rg * 4;
    const float* w1hb = w1h + rg * 4;

    for (int s = 0; s <= NL; s++) {
        // Prefetch layer-0 xg for this step (set-A gate threads)
        float xg0[4];
        if (tid < 128) {
            int t0 = (s < NL) ? s : (NL - 1);
            const float* xp = g_xg + (size_t)(t0 * 32 + bb) * NG;
#pragma unroll
            for (int q = 0; q < 4; q++) xg0[q] = __ldg(xp + rowq[q]);
        }

        // h pointers (previous-step state; buffers alternate)
        const float* h0p = g_h0 + (s & 1) * (NH * NB) + bg * 4;
        const float* h1p = g_h1 + ((s & 1) ^ 1) * (NH * NB) + bg * 4;

        // Merged GEMM with explicit 1-deep h register pipeline.
        unsigned long long A[8], Bv[8];
#pragma unroll
        for (int i = 0; i < 8; i++) { A[i] = 0ull; Bv[i] = 0ull; }

        float4 c0v = *(const float4*)(h0p + k0 * 32);
        float4 c1v = *(const float4*)(h1p + k0 * 32);
#pragma unroll 8
        for (int k = k0; k < k0 + 32; k++) {
            // issue next iteration's loads first (last one overreads into pad)
            float4 n0v = *(const float4*)(h0p + (k + 1) * 32);
            float4 n1v = *(const float4*)(h1p + (k + 1) * 32);

            unsigned long long d00 = pack2(c0v.x), d01 = pack2(c0v.y);
            unsigned long long d02 = pack2(c0v.z), d03 = pack2(c0v.w);
            unsigned long long d10 = pack2(c1v.x), d11 = pack2(c1v.y);
            unsigned long long d12 = pack2(c1v.z), d13 = pack2(c1v.w);

            ulonglong2 W0 = *(const ulonglong2*)(w0b + k * 16);
            A[0] = ffma2(W0.x, d00, A[0]); A[1] = ffma2(W0.x, d01, A[1]);
            A[2] = ffma2(W0.x, d02, A[2]); A[3] = ffma2(W0.x, d03, A[3]);
            A[4] = ffma2(W0.y, d00, A[4]); A[5] = ffma2(W0.y, d01, A[5]);
            A[6] = ffma2(W0.y, d02, A[6]); A[7] = ffma2(W0.y, d03, A[7]);

            ulonglong2 W1 = *(const ulonglong2*)(w1ib + k * 16);
            Bv[0] = ffma2(W1.x, d00, Bv[0]); Bv[1] = ffma2(W1.x, d01, Bv[1]);
            Bv[2] = ffma2(W1.x, d02, Bv[2]); Bv[3] = ffma2(W1.x, d03, Bv[3]);
            Bv[4] = ffma2(W1.y, d00, Bv[4]); Bv[5] = ffma2(W1.y, d01, Bv[5]);
            Bv[6] = ffma2(W1.y, d02, Bv[6]); Bv[7] = ffma2(W1.y, d03, Bv[7]);

            ulonglong2 W2 = *(const ulonglong2*)(w1hb + k * 16);
            Bv[0] = ffma2(W2.x, d10, Bv[0]); Bv[1] = ffma2(W2.x, d11, Bv[1]);
            Bv[2] = ffma2(W2.x, d12, Bv[2]); Bv[3] = ffma2(W2.x, d13, Bv[3]);
            Bv[4] = ffma2(W2.y, d10, Bv[4]); Bv[5] = ffma2(W2.y, d11, Bv[5]);
            Bv[6] = ffma2(W2.y, d12, Bv[6]); Bv[7] = ffma2(W2.y, d13, Bv[7]);

            c0v = n0v; c1v = n1v;
        }

        // Store partials: pair (p.x, p.y) = rows (rg*4+rp*2, +1), batch bg*4+j
#pragma unroll
        for (int rp = 0; rp < 2; rp++)
#pragma unroll
            for (int j = 0; j < 4; j++) {
                int b = bg * 4 + j;
                int r = rg * 4 + rp * 2;
                float2 p = unpack2(A[rp * 4 + j]);
                redA[(warp * 16 + r + 0) * 33 + b] = p.x;
                redA[(warp * 16 + r + 1) * 33 + b] = p.y;
                p = unpack2(Bv[rp * 4 + j]);
                redB[(warp * 16 + r + 0) * 33 + b] = p.x;
                redB[(warp * 16 + r + 1) * 33 + b] = p.y;
            }
        __syncthreads();

        // Fused reduce + gates (tid < 256: set A: tid<128 layer0, set B: layer1)
        if (tid < 256) {
            int j = cta * 4 + uu;
            if (gset == 0 && s < NL) {        // layer 0, t = s
                float gq[4];
#pragma unroll
                for (int q = 0; q < 4; q++) {
                    float acc = xg0[q];
                    const float* rp = redA + (q * 4 + uu) * 33 + bb;
#pragma unroll
                    for (int w = 0; w < 16; w++) acc += rp[w * 16 * 33];
                    gq[q] = acc;
                }
                float ig = sigm_f(gq[0]);
                float fg = sigm_f(gq[1]);
                float cg = tanh_f(gq[2]);
                float og = sigm_f(gq[3]);
                int ci = uu * 32 + bb;
                float c = fg * c0_s[ci] + ig * cg;
                c0_s[ci] = c;
                float h = og * tanh_f(c);
                g_h0[((s + 1) & 1) * (NH * NB) + j * 32 + bb] = h;
                if (s == NL - 1) {
                    d_out[bb * NH + j] = h;                               // hidden L0
                    d_out[NLAYERS * NB * NH + bb * NH + j] = c;           // cell  L0
                }
            }
            if (gset == 1 && s >= 1) {        // layer 1, t = s-1
                float gq[4];
#pragma unroll
                for (int q = 0; q < 4; q++) {
                    float acc = b1[q];
                    const float* rp = redB + (q * 4 + uu) * 33 + bb;
#pragma unroll
                    for (int w = 0; w < 16; w++) acc += rp[w * 16 * 33];
                    gq[q] = acc;
                }
                float ig = sigm_f(gq[0]);
                float fg = sigm_f(gq[1]);
                float cg = tanh_f(gq[2]);
                float og = sigm_f(gq[3]);
                int ci = uu * 32 + bb;
                float c = fg * c1_s[ci] + ig * cg;
                c1_s[ci] = c;
                float h = og * tanh_f(c);
                g_h1[(s & 1) * (NH * NB) + j * 32 + bb] = h;
                if (s == NL) {
                    d_out[NB * NH + bb * NH + j] = h;                     // hidden L1
                    d_out[NLAYERS * NB * NH + NB * NH + bb * NH + j] = c; // cell  L1
                }
            }
        }
        __syncthreads();

        // Grid-wide barrier: release-RED arrive (syncthreads above ordered the
        // gate threads' h stores), then acquire-poll. No MEMBAR needed.
        if (s < NL) {
            if (tid == 0) {
                asm volatile("red.release.gpu.global.add.s32 [%0], %1;"
                             :: "l"(&g_bar), "r"(1) : "memory");
                int target = 128 * (s + 1);
                int v;
                do {
                    asm volatile("ld.acquire.gpu.global.s32 %0, [%1];"
                                 : "=r"(v) : "l"(&g_bar) : "memory");
                } while (v < target);
            }
            __syncthreads();
        }
    }
}

// ---------------------------------------------------------------------------
// Launcher
// ---------------------------------------------------------------------------
extern "C" void kernel_launch(void* const* d_in, const int* in_sizes, int n_in,
                              void* d_out, int out_size) {
    const int*   tokens = (const int*)  d_in[0];
    const float* emb    = (const float*)d_in[1];
    const float* Wih    = (const float*)d_in[2];   // (2, 2048, 512)
    const float* Whh    = (const float*)d_in[3];   // (2, 2048, 512)
    const float* bih    = (const float*)d_in[4];   // (2, 2048)
    const float* bhh    = (const float*)d_in[5];   // (2, 2048)
    float* out = (float*)d_out;

    const int FUSED_SMEM = (3 * 512 * 16 + 2 * REDSZ + 256) * 4;   // 166912 B
    cudaFuncSetAttribute(lstm_fused, cudaFuncAttributeMaxDynamicSharedMemorySize,
                         FUSED_SMEM);

    dim3 ggrid(NG / 128, (NL * NB) / 128);   // (16, 128)

    // layer-0 input GEMM (embedding gather fused), then fused 2-layer recurrence
    xg_gemm<<<ggrid, 256>>>(emb, tokens, Wih, bih, bhh);
    init_kernel<<<64, 256>>>();
    lstm_fused<<<128, 512, FUSED_SMEM>>>(Whh, Wih, bih, bhh, out);
}